// round 15
// baseline (speedup 1.0000x reference)
#include <cuda_runtime.h>
#include <cuda_bf16.h>
#include <cstdint>

#define B_  2
#define T_  2048
#define S_  2048
#define D_  512
#define H_  8
#define HS_ 64
#define M_  (B_*T_)                 // 4096 rows
#define MD_ ((size_t)M_*D_)         // 2097152
#define DD_ ((size_t)D_*D_)         // 262144

// Scratch (allocations are forbidden; use device globals). Split-bf16 pairs.
__device__ __nv_bfloat16 g_acth[3*MD_], g_actl[3*MD_];   // converted inputs
__device__ __nv_bfloat16 g_wth [4*DD_], g_wtl [4*DD_];   // transposed weights [c][k]
__device__ __nv_bfloat16 g_qkvh[3*MD_], g_qkvl[3*MD_];   // q,k,v  [b][n][h][o]
__device__ __nv_bfloat16 g_mhh [MD_],   g_mhl [MD_];     // attention output

// ---------------------------------------------------------------------------
// helpers
// ---------------------------------------------------------------------------
__device__ __forceinline__ void mma16816(float c[4],
    uint32_t a0, uint32_t a1, uint32_t a2, uint32_t a3,
    uint32_t b0, uint32_t b1)
{
    asm volatile(
        "mma.sync.aligned.m16n8k16.row.col.f32.bf16.bf16.f32 "
        "{%0,%1,%2,%3}, {%4,%5,%6,%7}, {%8,%9}, {%0,%1,%2,%3};"
        : "+f"(c[0]), "+f"(c[1]), "+f"(c[2]), "+f"(c[3])
        : "r"(a0), "r"(a1), "r"(a2), "r"(a3), "r"(b0), "r"(b1));
}

__device__ __forceinline__ void ldsm4(uint32_t addr,
    uint32_t& r0, uint32_t& r1, uint32_t& r2, uint32_t& r3)
{
    asm volatile("ldmatrix.sync.aligned.m8n8.x4.shared.b16 {%0,%1,%2,%3}, [%4];"
        : "=r"(r0), "=r"(r1), "=r"(r2), "=r"(r3) : "r"(addr));
}

__device__ __forceinline__ void ldsm4t(uint32_t addr,
    uint32_t& r0, uint32_t& r1, uint32_t& r2, uint32_t& r3)
{
    asm volatile("ldmatrix.sync.aligned.m8n8.x4.trans.shared.b16 {%0,%1,%2,%3}, [%4];"
        : "=r"(r0), "=r"(r1), "=r"(r2), "=r"(r3) : "r"(addr));
}

__device__ __forceinline__ float ex2f(float x)
{
    float y;
    asm("ex2.approx.f32 %0, %1;" : "=f"(y) : "f"(x));
    return y;
}

__device__ __forceinline__ void pack_split(float a, float b, uint32_t& h, uint32_t& l)
{
    __nv_bfloat162 hh = __floats2bfloat162_rn(a, b);
    float fa = __bfloat162float(hh.x), fb = __bfloat162float(hh.y);
    __nv_bfloat162 ll = __floats2bfloat162_rn(a - fa, b - fb);
    h = *reinterpret_cast<uint32_t*>(&hh);
    l = *reinterpret_cast<uint32_t*>(&ll);
}

__device__ __forceinline__ void cp16(uint32_t dst, const void* src)
{
    asm volatile("cp.async.cg.shared.global [%0], [%1], 16;" :: "r"(dst), "l"(src));
}
#define CP_COMMIT() asm volatile("cp.async.commit_group;" ::: "memory")
#define CP_WAIT0()  asm volatile("cp.async.wait_group 0;" ::: "memory")
#define CP_WAIT1()  asm volatile("cp.async.wait_group 1;" ::: "memory")

// ---------------------------------------------------------------------------
// prep_act: fp32 inputs -> split bf16 (one-time)
// ---------------------------------------------------------------------------
__global__ __launch_bounds__(256)
void prep_act(const float* __restrict__ q, const float* __restrict__ k,
              const float* __restrict__ v)
{
    int z = blockIdx.z;
    const float* in = (z == 0) ? q : (z == 1) ? k : v;
    size_t e = (size_t)blockIdx.x * 256 + threadIdx.x;    // float4 index
    float4 a = reinterpret_cast<const float4*>(in)[e];
    uint32_t h0, l0, h1, l1;
    pack_split(a.x, a.y, h0, l0);
    pack_split(a.z, a.w, h1, l1);
    reinterpret_cast<uint2*>(g_acth + (size_t)z * MD_)[e] = make_uint2(h0, h1);
    reinterpret_cast<uint2*>(g_actl + (size_t)z * MD_)[e] = make_uint2(l0, l1);
}

// ---------------------------------------------------------------------------
// prep_w: weights -> transposed split bf16 Wt[c][k] (one-time)
// ---------------------------------------------------------------------------
__global__ __launch_bounds__(256)
void prep_w(const float* __restrict__ qk, const float* __restrict__ kk,
            const float* __restrict__ vk, const float* __restrict__ pk)
{
    __shared__ float ts[64 * 66];
    const int z = blockIdx.z;
    const int x = blockIdx.x;      // 0..63
    const int tid = threadIdx.x;
    const float* in = (z == 0) ? qk : (z == 1) ? kk : (z == 2) ? vk : pk;
    int k0, cbase;
    if (z < 3) { k0 = (x & 7) * 64; cbase = (x >> 3) * 64; }
    else       { k0 = (x >> 3) * 64; cbase = (x & 7) * 64; }

    #pragma unroll
    for (int it = 0; it < 4; it++) {
        int e = tid + it * 256;
        int i = e >> 4, j4 = e & 15;
        float4 a;
        if (z < 3)
            a = *reinterpret_cast<const float4*>(in + (size_t)(x >> 3) * (D_ * HS_)
                                                 + (size_t)(k0 + i) * HS_ + j4 * 4);
        else
            a = *reinterpret_cast<const float4*>(in + (size_t)(k0 + i) * D_ + cbase + j4 * 4);
        int wo = i * 66 + j4 * 4;
        *reinterpret_cast<float2*>(ts + wo)     = make_float2(a.x, a.y);
        *reinterpret_cast<float2*>(ts + wo + 2) = make_float2(a.z, a.w);
    }
    __syncthreads();

    #pragma unroll
    for (int it = 0; it < 2; it++) {
        int e = tid + it * 256;
        int o = e >> 3, k8 = e & 7;
        uint32_t hw[4], lw[4];
        #pragma unroll
        for (int p = 0; p < 4; p++) {
            float f0 = ts[(k8 * 8 + 2 * p)     * 66 + o];
            float f1 = ts[(k8 * 8 + 2 * p + 1) * 66 + o];
            pack_split(f0, f1, hw[p], lw[p]);
        }
        size_t off = (size_t)z * DD_ + (size_t)(cbase + o) * D_ + k0 + k8 * 8;
        *reinterpret_cast<uint4*>(g_wth + off) = *reinterpret_cast<uint4*>(hw);
        *reinterpret_cast<uint4*>(g_wtl + off) = *reinterpret_cast<uint4*>(lw);
    }
}

// ---------------------------------------------------------------------------
// gemm_bf16<WN>: CTA tile 128 x (WN*32), K-tile 32, cp.async 2-stage pipeline,
// ldmatrix fragment loads. 8 warps as (8/WN)m x WNn. 2 CTAs/SM.
// ---------------------------------------------------------------------------
#define PS_W 20

template<int WN>
__global__ __launch_bounds__(256, 2)
void gemm_bf16(const __nv_bfloat16* __restrict__ Ah, const __nv_bfloat16* __restrict__ Al,
               const __nv_bfloat16* __restrict__ Wth, const __nv_bfloat16* __restrict__ Wtl,
               __nv_bfloat16* __restrict__ Ch, __nv_bfloat16* __restrict__ Cl,
               float* __restrict__ Cf, const float* __restrict__ bias, float qscale)
{
    constexpr int NCOL  = WN * 32;
    constexpr int MT    = 128 / ((8 / WN) * 16);
    constexpr int A_ARR = 128 * PS_W;
    constexpr int W_ARR = NCOL * PS_W;
    constexpr int STAGE = 2 * A_ARR + 2 * W_ARR;

    extern __shared__ __align__(16) uint32_t sm[];

    const int z = blockIdx.z;
    Ah  += (size_t)z * MD_;  Al  += (size_t)z * MD_;
    Wth += (size_t)z * DD_;  Wtl += (size_t)z * DD_;

    const int tid = threadIdx.x;
    const int w = tid >> 5, lane = tid & 31, g = lane >> 2, t = lane & 3;
    const int wm = w / WN, wn = w % WN;
    const int m0 = blockIdx.x * 128, c0 = blockIdx.y * NCOL;

    const uint32_t smb = (uint32_t)__cvta_generic_to_shared(sm);
    const int r_ld = tid >> 2, c4_ld = tid & 3;

    auto issue = [&](int kt, int st) {
        uint32_t base = smb + st * (STAGE * 4);
        #pragma unroll
        for (int i = 0; i < 2; i++) {
            int r = r_ld + i * 64;
            uint32_t d = base + r * (PS_W * 4) + c4_ld * 16;
            size_t ga = (size_t)(m0 + r) * D_ + kt + c4_ld * 8;
            cp16(d,             Ah + ga);
            cp16(d + A_ARR * 4, Al + ga);
        }
        #pragma unroll
        for (int i = 0; i < NCOL / 64; i++) {
            int r = r_ld + i * 64;
            uint32_t d = base + (2 * A_ARR) * 4 + r * (PS_W * 4) + c4_ld * 16;
            size_t gw = (size_t)(c0 + r) * D_ + kt + c4_ld * 8;
            cp16(d,             Wth + gw);
            cp16(d + W_ARR * 4, Wtl + gw);
        }
    };

    const int mLd = lane >> 3, rLd = lane & 7;
    const uint32_t aSkel = ((wm * (16 * MT) + (mLd & 1) * 8 + rLd) * PS_W + (mLd >> 1) * 4) * 4;
    const uint32_t bSkel = ((wn * 32 + rLd) * PS_W + (mLd & 1) * 4) * 4
                         + (2 * A_ARR + (mLd >> 1) * W_ARR) * 4;

    float acc[MT * 4][4];
    #pragma unroll
    for (int i = 0; i < MT * 4; i++)
        #pragma unroll
        for (int j = 0; j < 4; j++) acc[i][j] = 0.f;

    issue(0, 0);
    CP_COMMIT();

    for (int it = 0; it < D_ / 32; ++it) {
        CP_WAIT0();
        __syncthreads();
        if (it + 1 < D_ / 32) { issue((it + 1) * 32, (it + 1) & 1); CP_COMMIT(); }

        const uint32_t stage = smb + (it & 1) * (STAGE * 4);

        #pragma unroll
        for (int kc = 0; kc < 2; kc++) {
            uint32_t fah[MT][4], fal[MT][4];
            #pragma unroll
            for (int mt = 0; mt < MT; mt++) {
                uint32_t a = stage + aSkel + (mt * 16 * PS_W + kc * 8) * 4;
                ldsm4(a,             fah[mt][0], fah[mt][1], fah[mt][2], fah[mt][3]);
                ldsm4(a + A_ARR * 4, fal[mt][0], fal[mt][1], fal[mt][2], fal[mt][3]);
            }
            #pragma unroll
            for (int nt = 0; nt < 4; nt++) {
                uint32_t b0, b1, b2, b3;
                ldsm4(stage + bSkel + (nt * 8 * PS_W + kc * 8) * 4, b0, b1, b2, b3);
                #pragma unroll
                for (int mt = 0; mt < MT; mt++) {
                    float* a = acc[mt * 4 + nt];
                    mma16816(a, fah[mt][0], fah[mt][1], fah[mt][2], fah[mt][3], b0, b1);
                    mma16816(a, fah[mt][0], fah[mt][1], fah[mt][2], fah[mt][3], b2, b3);
                    mma16816(a, fal[mt][0], fal[mt][1], fal[mt][2], fal[mt][3], b0, b1);
                }
            }
        }
    }

    const float scale = (z == 0) ? qscale : 1.0f;
    #pragma unroll
    for (int mt = 0; mt < MT; mt++) {
        int row0 = m0 + wm * (16 * MT) + mt * 16 + g;
        #pragma unroll
        for (int nt = 0; nt < 4; nt++) {
            int col = c0 + wn * 32 + nt * 8 + 2 * t;
            float* a = acc[mt * 4 + nt];
            if (Cf) {
                float b0 = bias ? bias[col] : 0.f;
                float b1 = bias ? bias[col + 1] : 0.f;
                *reinterpret_cast<float2*>(Cf + (size_t)row0 * D_ + col) =
                    make_float2(a[0] + b0, a[1] + b1);
                *reinterpret_cast<float2*>(Cf + (size_t)(row0 + 8) * D_ + col) =
                    make_float2(a[2] + b0, a[3] + b1);
            } else {
                uint32_t h0, l0, h1, l1;
                pack_split(a[0] * scale, a[1] * scale, h0, l0);
                pack_split(a[2] * scale, a[3] * scale, h1, l1);
                size_t o0 = (size_t)z * MD_ + (size_t)row0 * D_ + col;
                size_t o1 = (size_t)z * MD_ + (size_t)(row0 + 8) * D_ + col;
                *reinterpret_cast<uint32_t*>(Ch + o0) = h0;
                *reinterpret_cast<uint32_t*>(Cl + o0) = l0;
                *reinterpret_cast<uint32_t*>(Ch + o1) = h1;
                *reinterpret_cast<uint32_t*>(Cl + o1) = l1;
            }
        }
    }
}

#define SMEM_GEMM2 (2 * (2 * 128 * PS_W + 2 * 64 * PS_W) * 4)       // 61440

// ---------------------------------------------------------------------------
// attn: 128 threads (4 warps), q-tile 128 (32 rows/warp), KV tile 32,
// 4-stage cp.async ring, SKEWED pipeline: iteration it issues QK(it) then
// PV(it-1) (packed P held in registers), then softmax(it) overlaps the
// tensor backlog. One barrier/iter. 2 CTAs/SM.
// ---------------------------------------------------------------------------
#define AS_W 36
#define KT_ 32
#define A_KARR (KT_ * AS_W)                 // 1152 words
#define A_STAGE (4 * A_KARR)                // 4608 words / stage
#define A_QWORDS (2 * 128 * AS_W)           // 9216 words
#define NSTG 4
#define SMEM_ATTN ((A_QWORDS + NSTG * A_STAGE) * 4)   // 110592 B

__global__ __launch_bounds__(128, 2)
void attn_mma(const __nv_bfloat16* __restrict__ Qh, const __nv_bfloat16* __restrict__ Ql,
              const __nv_bfloat16* __restrict__ Kh, const __nv_bfloat16* __restrict__ Kl,
              const __nv_bfloat16* __restrict__ Vh, const __nv_bfloat16* __restrict__ Vl,
              __nv_bfloat16* __restrict__ Oh, __nv_bfloat16* __restrict__ Ol)
{
    extern __shared__ __align__(16) uint32_t sm[];

    const int tid = threadIdx.x;
    const int w = tid >> 5, lane = tid & 31, g = lane >> 2, t = lane & 3;
    const int n0 = blockIdx.x * 128;
    const int h = blockIdx.y, b = blockIdx.z;
    const size_t rs = (size_t)H_ * HS_;   // 512
    const size_t qbase = (((size_t)b * T_ + n0) * H_ + h) * HS_;
    const size_t kbase = ((size_t)b * S_) * rs + (size_t)h * HS_;

    const uint32_t smb = (uint32_t)__cvta_generic_to_shared(sm);
    const int r_ld = tid >> 3, c8_ld = tid & 7;

    auto issue_kv = [&](int it, int st) {
        uint32_t base = smb + (A_QWORDS + st * A_STAGE) * 4;
        const size_t kb = kbase + (size_t)(it * KT_) * rs;
        #pragma unroll
        for (int i = 0; i < 2; i++) {
            int r = r_ld + i * 16;
            uint32_t d = base + r * (AS_W * 4) + c8_ld * 16;
            size_t src = kb + (size_t)r * rs + c8_ld * 8;
            cp16(d,                  Kh + src);
            cp16(d + A_KARR * 4,     Kl + src);
            cp16(d + 2 * A_KARR * 4, Vh + src);
            cp16(d + 3 * A_KARR * 4, Vl + src);
        }
    };

    // ---- Q tile (128x64 hi/lo) + stage0 (group0), stage1 (group1) ----
    {
        #pragma unroll
        for (int i = 0; i < 8; i++) {
            int r = r_ld + i * 16;
            uint32_t d = smb + r * (AS_W * 4) + c8_ld * 16;
            size_t src = qbase + (size_t)r * rs + c8_ld * 8;
            cp16(d, Qh + src);
            cp16(d + 128 * AS_W * 4, Ql + src);
        }
        issue_kv(0, 0);
        CP_COMMIT();
        issue_kv(1, 1);
        CP_COMMIT();
    }

    const int rowA = w * 32;

    const int mLd = lane >> 3, rLd = lane & 7;
    const uint32_t qA_hi = smb + ((rowA + (mLd & 1) * 8 + rLd) * AS_W + (mLd >> 1) * 4) * 4;
    const uint32_t qA_lo = qA_hi + 128 * AS_W * 4;
    const uint32_t bSkelK = (rLd * AS_W + (mLd & 1) * 4 + ((mLd >> 1) ? A_KARR : 0)) * 4;
    const uint32_t bSkelV = (((mLd & 1) * 8 + rLd) * AS_W + ((mLd >> 1) ? A_KARR : 0)) * 4;

    float oacc[2][8][4];
    #pragma unroll
    for (int mf = 0; mf < 2; mf++)
        #pragma unroll
        for (int ot = 0; ot < 8; ot++)
            #pragma unroll
            for (int j = 0; j < 4; j++) oacc[mf][ot][j] = 0.f;
    float ls[2][2] = {{0.f, 0.f}, {0.f, 0.f}};

    uint32_t pph[2][8], ppl[2][8];   // packed P(it-1): [mf][kc*4+j]

    const int NIT = S_ / KT_;   // 64
    for (int it = 0; it < NIT; ++it) {
        CP_WAIT1();              // stage it complete (stage it+1 may be in flight)
        __syncthreads();         // publish; also: all warps done with iter it-1
        if (it + 2 < NIT) { issue_kv(it + 2, (it + 2) & 3); CP_COMMIT(); }

        const uint32_t kvb = smb + (A_QWORDS + (it & 3) * A_STAGE) * 4;

        // ---- QK(it): S = Q K^T ----
        float acc[2][4][4];
        #pragma unroll
        for (int mf = 0; mf < 2; mf++)
            #pragma unroll
            for (int nt = 0; nt < 4; nt++)
                #pragma unroll
                for (int j = 0; j < 4; j++) acc[mf][nt][j] = 0.f;

        #pragma unroll
        for (int kc = 0; kc < 4; kc++) {
            uint32_t ah[2][4], al[2][4];
            #pragma unroll
            for (int mf = 0; mf < 2; mf++) {
                uint32_t ao = (uint32_t)(mf * 16 * AS_W * 4) + kc * 32;
                ldsm4(qA_hi + ao, ah[mf][0], ah[mf][1], ah[mf][2], ah[mf][3]);
                ldsm4(qA_lo + ao, al[mf][0], al[mf][1], al[mf][2], al[mf][3]);
            }
            #pragma unroll
            for (int nt = 0; nt < 4; nt++) {
                uint32_t b0, b1, b2, b3;
                ldsm4(kvb + bSkelK + (nt * 8 * AS_W + kc * 8) * 4, b0, b1, b2, b3);
                #pragma unroll
                for (int mf = 0; mf < 2; mf++) {
                    mma16816(acc[mf][nt], ah[mf][0], ah[mf][1], ah[mf][2], ah[mf][3], b0, b1);
                    mma16816(acc[mf][nt], ah[mf][0], ah[mf][1], ah[mf][2], ah[mf][3], b2, b3);
                    mma16816(acc[mf][nt], al[mf][0], al[mf][1], al[mf][2], al[mf][3], b0, b1);
                }
            }
        }

        // ---- PV(it-1): independent of softmax(it); fills tensor pipe ----
        if (it > 0) {
            const uint32_t vbb = smb + (A_QWORDS + ((it - 1) & 3) * A_STAGE
                                        + 2 * A_KARR) * 4;
            #pragma unroll
            for (int kc = 0; kc < 2; kc++) {
                #pragma unroll
                for (int ot = 0; ot < 8; ot++) {
                    uint32_t b0, b1, b2, b3;
                    ldsm4t(vbb + bSkelV + (kc * 16 * AS_W + ot * 4) * 4, b0, b1, b2, b3);
                    #pragma unroll
                    for (int mf = 0; mf < 2; mf++) {
                        mma16816(oacc[mf][ot], pph[mf][kc*4+0], pph[mf][kc*4+1],
                                 pph[mf][kc*4+2], pph[mf][kc*4+3], b0, b1);
                        mma16816(oacc[mf][ot], pph[mf][kc*4+0], pph[mf][kc*4+1],
                                 pph[mf][kc*4+2], pph[mf][kc*4+3], b2, b3);
                        mma16816(oacc[mf][ot], ppl[mf][kc*4+0], ppl[mf][kc*4+1],
                                 ppl[mf][kc*4+2], ppl[mf][kc*4+3], b0, b1);
                    }
                }
            }
        }

        // ---- softmax(it): p = 2^s; pack into persistent P registers ----
        #pragma unroll
        for (int mf = 0; mf < 2; mf++)
            #pragma unroll
            for (int nt = 0; nt < 4; nt++) {
                float p0 = ex2f(acc[mf][nt][0]);
                float p1 = ex2f(acc[mf][nt][1]);
                float p2 = ex2f(acc[mf][nt][2]);
                float p3 = ex2f(acc[mf][nt][3]);
                ls[mf][0] += p0 + p1;
                ls[mf][1] += p2 + p3;
                acc[mf][nt][0] = p0; acc[mf][nt][1] = p1;
                acc[mf][nt][2] = p2; acc[mf][nt][3] = p3;
            }
        #pragma unroll
        for (int mf = 0; mf < 2; mf++)
            #pragma unroll
            for (int kc = 0; kc < 2; kc++) {
                pack_split(acc[mf][2*kc][0],   acc[mf][2*kc][1],   pph[mf][kc*4+0], ppl[mf][kc*4+0]);
                pack_split(acc[mf][2*kc][2],   acc[mf][2*kc][3],   pph[mf][kc*4+1], ppl[mf][kc*4+1]);
                pack_split(acc[mf][2*kc+1][0], acc[mf][2*kc+1][1], pph[mf][kc*4+2], ppl[mf][kc*4+2]);
                pack_split(acc[mf][2*kc+1][2], acc[mf][2*kc+1][3], pph[mf][kc*4+3], ppl[mf][kc*4+3]);
            }
    }

    // ---- epilogue: PV(NIT-1) ----
    {
        const uint32_t vbb = smb + (A_QWORDS + ((NIT - 1) & 3) * A_STAGE
                                    + 2 * A_KARR) * 4;
        #pragma unroll
        for (int kc = 0; kc < 2; kc++) {
            #pragma unroll
            for (int ot = 0; ot < 8; ot++) {
                uint32_t b0, b1, b2, b3;
                ldsm4t(vbb + bSkelV + (kc * 16 * AS_W + ot * 4) * 4, b0, b1, b2, b3);
                #pragma unroll
                for (int mf = 0; mf < 2; mf++) {
                    mma16816(oacc[mf][ot], pph[mf][kc*4+0], pph[mf][kc*4+1],
                             pph[mf][kc*4+2], pph[mf][kc*4+3], b0, b1);
                    mma16816(oacc[mf][ot], pph[mf][kc*4+0], pph[mf][kc*4+1],
                             pph[mf][kc*4+2], pph[mf][kc*4+3], b2, b3);
                    mma16816(oacc[mf][ot], ppl[mf][kc*4+0], ppl[mf][kc*4+1],
                             ppl[mf][kc*4+2], ppl[mf][kc*4+3], b0, b1);
                }
            }
        }
    }

    // ---- normalize, split, write mh ----
    #pragma unroll
    for (int mf = 0; mf < 2; mf++) {
        ls[mf][0] += __shfl_xor_sync(0xffffffffu, ls[mf][0], 1);
        ls[mf][0] += __shfl_xor_sync(0xffffffffu, ls[mf][0], 2);
        ls[mf][1] += __shfl_xor_sync(0xffffffffu, ls[mf][1], 1);
        ls[mf][1] += __shfl_xor_sync(0xffffffffu, ls[mf][1], 2);
        const float inv0 = 1.f / ls[mf][0];
        const float inv1 = 1.f / ls[mf][1];

        size_t or0 = qbase + (size_t)(rowA + mf * 16 + g) * rs;
        size_t or1 = qbase + (size_t)(rowA + mf * 16 + g + 8) * rs;
        #pragma unroll
        for (int ot = 0; ot < 8; ot++) {
            uint32_t h0, l0, h1, l1;
            pack_split(oacc[mf][ot][0] * inv0, oacc[mf][ot][1] * inv0, h0, l0);
            pack_split(oacc[mf][ot][2] * inv1, oacc[mf][ot][3] * inv1, h1, l1);
            int col = ot * 8 + 2 * t;
            *reinterpret_cast<uint32_t*>(Oh + or0 + col) = h0;
            *reinterpret_cast<uint32_t*>(Ol + or0 + col) = l0;
            *reinterpret_cast<uint32_t*>(Oh + or1 + col) = h1;
            *reinterpret_cast<uint32_t*>(Ol + or1 + col) = l1;
        }
    }
}

// ---------------------------------------------------------------------------
// Host launcher
// ---------------------------------------------------------------------------
extern "C" void kernel_launch(void* const* d_in, const int* in_sizes, int n_in,
                              void* d_out, int out_size)
{
    const float* query = (const float*)d_in[0];
    const float* key   = (const float*)d_in[1];
    const float* value = (const float*)d_in[2];
    const float* qkern = (const float*)d_in[3];
    const float* kkern = (const float*)d_in[4];
    const float* vkern = (const float*)d_in[5];
    const float* pkern = (const float*)d_in[6];
    const float* pbias = (const float*)d_in[7];
    float* out = (float*)d_out;

    __nv_bfloat16 *acth, *actl, *wth, *wtl, *qkvh, *qkvl, *mhh, *mhl;
    cudaGetSymbolAddress((void**)&acth, g_acth);
    cudaGetSymbolAddress((void**)&actl, g_actl);
    cudaGetSymbolAddress((void**)&wth,  g_wth);
    cudaGetSymbolAddress((void**)&wtl,  g_wtl);
    cudaGetSymbolAddress((void**)&qkvh, g_qkvh);
    cudaGetSymbolAddress((void**)&qkvl, g_qkvl);
    cudaGetSymbolAddress((void**)&mhh,  g_mhh);
    cudaGetSymbolAddress((void**)&mhl,  g_mhl);

    cudaFuncSetAttribute(gemm_bf16<2>, cudaFuncAttributeMaxDynamicSharedMemorySize, SMEM_GEMM2);
    cudaFuncSetAttribute(attn_mma,     cudaFuncAttributeMaxDynamicSharedMemorySize, SMEM_ATTN);

    // 1. one-time conversions
    prep_act<<<dim3(2048, 1, 3), 256>>>(query, key, value);
    prep_w  <<<dim3(64, 1, 4),   256>>>(qkern, kkern, vkern, pkern);

    // 2. fused QKV projection; q scale = (1/sqrt(HS)) * log2(e) for exp2 softmax
    const float qsc = 0.125f * 1.4426950408889634f;
    gemm_bf16<2><<<dim3(32, 8, 3), 256, SMEM_GEMM2>>>(acth, actl, wth, wtl,
                                                      qkvh, qkvl, nullptr, nullptr, qsc);

    // 3. attention (skewed pipeline, 256 CTAs x 128 threads, 2 CTAs/SM)
    attn_mma<<<dim3(16, 8, 2), 128, SMEM_ATTN>>>(qkvh, qkvl,
                                                 qkvh + MD_, qkvl + MD_,
                                                 qkvh + 2 * MD_, qkvl + 2 * MD_,
                                                 mhh, mhl);

    // 4. output projection (fp32 + bias)
    gemm_bf16<2><<<dim3(32, 8, 1), 256, SMEM_GEMM2>>>(mhh, mhl, wth + 3 * DD_, wtl + 3 * DD_,
                                                      nullptr, nullptr, out, pbias, 1.0f);
}

// round 16
// speedup vs baseline: 1.0587x; 1.0587x over previous
#include <cuda_runtime.h>
#include <cuda_bf16.h>
#include <cstdint>

#define B_  2
#define T_  2048
#define S_  2048
#define D_  512
#define H_  8
#define HS_ 64
#define M_  (B_*T_)                 // 4096 rows
#define MD_ ((size_t)M_*D_)         // 2097152
#define DD_ ((size_t)D_*D_)         // 262144

// Scratch (allocations are forbidden; use device globals). Split-bf16 pairs.
__device__ __nv_bfloat16 g_acth[3*MD_], g_actl[3*MD_];   // converted inputs
__device__ __nv_bfloat16 g_wth [4*DD_], g_wtl [4*DD_];   // transposed weights [c][k]
__device__ __nv_bfloat16 g_qkvh[3*MD_], g_qkvl[3*MD_];   // q,k,v  [b][n][h][o]
__device__ __nv_bfloat16 g_mhh [MD_],   g_mhl [MD_];     // attention output

// ---------------------------------------------------------------------------
// helpers
// ---------------------------------------------------------------------------
__device__ __forceinline__ void mma16816(float c[4],
    uint32_t a0, uint32_t a1, uint32_t a2, uint32_t a3,
    uint32_t b0, uint32_t b1)
{
    asm volatile(
        "mma.sync.aligned.m16n8k16.row.col.f32.bf16.bf16.f32 "
        "{%0,%1,%2,%3}, {%4,%5,%6,%7}, {%8,%9}, {%0,%1,%2,%3};"
        : "+f"(c[0]), "+f"(c[1]), "+f"(c[2]), "+f"(c[3])
        : "r"(a0), "r"(a1), "r"(a2), "r"(a3), "r"(b0), "r"(b1));
}

__device__ __forceinline__ void ldsm4(uint32_t addr,
    uint32_t& r0, uint32_t& r1, uint32_t& r2, uint32_t& r3)
{
    asm volatile("ldmatrix.sync.aligned.m8n8.x4.shared.b16 {%0,%1,%2,%3}, [%4];"
        : "=r"(r0), "=r"(r1), "=r"(r2), "=r"(r3) : "r"(addr));
}

__device__ __forceinline__ void ldsm4t(uint32_t addr,
    uint32_t& r0, uint32_t& r1, uint32_t& r2, uint32_t& r3)
{
    asm volatile("ldmatrix.sync.aligned.m8n8.x4.trans.shared.b16 {%0,%1,%2,%3}, [%4];"
        : "=r"(r0), "=r"(r1), "=r"(r2), "=r"(r3) : "r"(addr));
}

__device__ __forceinline__ float ex2f(float x)
{
    float y;
    asm("ex2.approx.f32 %0, %1;" : "=f"(y) : "f"(x));
    return y;
}

__device__ __forceinline__ void pack_split(float a, float b, uint32_t& h, uint32_t& l)
{
    __nv_bfloat162 hh = __floats2bfloat162_rn(a, b);
    float fa = __bfloat162float(hh.x), fb = __bfloat162float(hh.y);
    __nv_bfloat162 ll = __floats2bfloat162_rn(a - fa, b - fb);
    h = *reinterpret_cast<uint32_t*>(&hh);
    l = *reinterpret_cast<uint32_t*>(&ll);
}

__device__ __forceinline__ void cp16(uint32_t dst, const void* src)
{
    asm volatile("cp.async.cg.shared.global [%0], [%1], 16;" :: "r"(dst), "l"(src));
}
#define CP_COMMIT() asm volatile("cp.async.commit_group;" ::: "memory")
#define CP_WAIT0()  asm volatile("cp.async.wait_group 0;" ::: "memory")

// ---------------------------------------------------------------------------
// prep_act: fp32 inputs -> split bf16 (one-time)
// ---------------------------------------------------------------------------
__global__ __launch_bounds__(256)
void prep_act(const float* __restrict__ q, const float* __restrict__ k,
              const float* __restrict__ v)
{
    int z = blockIdx.z;
    const float* in = (z == 0) ? q : (z == 1) ? k : v;
    size_t e = (size_t)blockIdx.x * 256 + threadIdx.x;    // float4 index
    float4 a = reinterpret_cast<const float4*>(in)[e];
    uint32_t h0, l0, h1, l1;
    pack_split(a.x, a.y, h0, l0);
    pack_split(a.z, a.w, h1, l1);
    reinterpret_cast<uint2*>(g_acth + (size_t)z * MD_)[e] = make_uint2(h0, h1);
    reinterpret_cast<uint2*>(g_actl + (size_t)z * MD_)[e] = make_uint2(l0, l1);
}

// ---------------------------------------------------------------------------
// prep_w: weights -> transposed split bf16 Wt[c][k] (one-time)
// ---------------------------------------------------------------------------
__global__ __launch_bounds__(256)
void prep_w(const float* __restrict__ qk, const float* __restrict__ kk,
            const float* __restrict__ vk, const float* __restrict__ pk)
{
    __shared__ float ts[64 * 66];
    const int z = blockIdx.z;
    const int x = blockIdx.x;      // 0..63
    const int tid = threadIdx.x;
    const float* in = (z == 0) ? qk : (z == 1) ? kk : (z == 2) ? vk : pk;
    int k0, cbase;
    if (z < 3) { k0 = (x & 7) * 64; cbase = (x >> 3) * 64; }
    else       { k0 = (x >> 3) * 64; cbase = (x & 7) * 64; }

    #pragma unroll
    for (int it = 0; it < 4; it++) {
        int e = tid + it * 256;
        int i = e >> 4, j4 = e & 15;
        float4 a;
        if (z < 3)
            a = *reinterpret_cast<const float4*>(in + (size_t)(x >> 3) * (D_ * HS_)
                                                 + (size_t)(k0 + i) * HS_ + j4 * 4);
        else
            a = *reinterpret_cast<const float4*>(in + (size_t)(k0 + i) * D_ + cbase + j4 * 4);
        int wo = i * 66 + j4 * 4;
        *reinterpret_cast<float2*>(ts + wo)     = make_float2(a.x, a.y);
        *reinterpret_cast<float2*>(ts + wo + 2) = make_float2(a.z, a.w);
    }
    __syncthreads();

    #pragma unroll
    for (int it = 0; it < 2; it++) {
        int e = tid + it * 256;
        int o = e >> 3, k8 = e & 7;
        uint32_t hw[4], lw[4];
        #pragma unroll
        for (int p = 0; p < 4; p++) {
            float f0 = ts[(k8 * 8 + 2 * p)     * 66 + o];
            float f1 = ts[(k8 * 8 + 2 * p + 1) * 66 + o];
            pack_split(f0, f1, hw[p], lw[p]);
        }
        size_t off = (size_t)z * DD_ + (size_t)(cbase + o) * D_ + k0 + k8 * 8;
        *reinterpret_cast<uint4*>(g_wth + off) = *reinterpret_cast<uint4*>(hw);
        *reinterpret_cast<uint4*>(g_wtl + off) = *reinterpret_cast<uint4*>(lw);
    }
}

// ---------------------------------------------------------------------------
// gemm_bf16<WN>: CTA tile 128 x (WN*32), K-tile 32, cp.async 2-stage pipeline,
// ldmatrix fragment loads. 8 warps as (8/WN)m x WNn. 2 CTAs/SM.
// WN=4 chosen: halves activation L2 re-reads vs WN=2 and gives 4:1 MMA:LDSM.
// ---------------------------------------------------------------------------
#define PS_W 20

template<int WN>
__global__ __launch_bounds__(256, 2)
void gemm_bf16(const __nv_bfloat16* __restrict__ Ah, const __nv_bfloat16* __restrict__ Al,
               const __nv_bfloat16* __restrict__ Wth, const __nv_bfloat16* __restrict__ Wtl,
               __nv_bfloat16* __restrict__ Ch, __nv_bfloat16* __restrict__ Cl,
               float* __restrict__ Cf, const float* __restrict__ bias, float qscale)
{
    constexpr int NCOL  = WN * 32;
    constexpr int MT    = 128 / ((8 / WN) * 16);
    constexpr int A_ARR = 128 * PS_W;
    constexpr int W_ARR = NCOL * PS_W;
    constexpr int STAGE = 2 * A_ARR + 2 * W_ARR;

    extern __shared__ __align__(16) uint32_t sm[];

    const int z = blockIdx.z;
    Ah  += (size_t)z * MD_;  Al  += (size_t)z * MD_;
    Wth += (size_t)z * DD_;  Wtl += (size_t)z * DD_;

    const int tid = threadIdx.x;
    const int w = tid >> 5, lane = tid & 31, g = lane >> 2, t = lane & 3;
    const int wm = w / WN, wn = w % WN;
    const int m0 = blockIdx.x * 128, c0 = blockIdx.y * NCOL;

    const uint32_t smb = (uint32_t)__cvta_generic_to_shared(sm);
    const int r_ld = tid >> 2, c4_ld = tid & 3;

    auto issue = [&](int kt, int st) {
        uint32_t base = smb + st * (STAGE * 4);
        #pragma unroll
        for (int i = 0; i < 2; i++) {
            int r = r_ld + i * 64;
            uint32_t d = base + r * (PS_W * 4) + c4_ld * 16;
            size_t ga = (size_t)(m0 + r) * D_ + kt + c4_ld * 8;
            cp16(d,             Ah + ga);
            cp16(d + A_ARR * 4, Al + ga);
        }
        #pragma unroll
        for (int i = 0; i < NCOL / 64; i++) {
            int r = r_ld + i * 64;
            uint32_t d = base + (2 * A_ARR) * 4 + r * (PS_W * 4) + c4_ld * 16;
            size_t gw = (size_t)(c0 + r) * D_ + kt + c4_ld * 8;
            cp16(d,             Wth + gw);
            cp16(d + W_ARR * 4, Wtl + gw);
        }
    };

    const int mLd = lane >> 3, rLd = lane & 7;
    const uint32_t aSkel = ((wm * (16 * MT) + (mLd & 1) * 8 + rLd) * PS_W + (mLd >> 1) * 4) * 4;
    const uint32_t bSkel = ((wn * 32 + rLd) * PS_W + (mLd & 1) * 4) * 4
                         + (2 * A_ARR + (mLd >> 1) * W_ARR) * 4;

    float acc[MT * 4][4];
    #pragma unroll
    for (int i = 0; i < MT * 4; i++)
        #pragma unroll
        for (int j = 0; j < 4; j++) acc[i][j] = 0.f;

    issue(0, 0);
    CP_COMMIT();

    for (int it = 0; it < D_ / 32; ++it) {
        CP_WAIT0();
        __syncthreads();
        if (it + 1 < D_ / 32) { issue((it + 1) * 32, (it + 1) & 1); CP_COMMIT(); }

        const uint32_t stage = smb + (it & 1) * (STAGE * 4);

        #pragma unroll
        for (int kc = 0; kc < 2; kc++) {
            uint32_t fah[MT][4], fal[MT][4];
            #pragma unroll
            for (int mt = 0; mt < MT; mt++) {
                uint32_t a = stage + aSkel + (mt * 16 * PS_W + kc * 8) * 4;
                ldsm4(a,             fah[mt][0], fah[mt][1], fah[mt][2], fah[mt][3]);
                ldsm4(a + A_ARR * 4, fal[mt][0], fal[mt][1], fal[mt][2], fal[mt][3]);
            }
            #pragma unroll
            for (int nt = 0; nt < 4; nt++) {
                uint32_t b0, b1, b2, b3;
                ldsm4(stage + bSkel + (nt * 8 * PS_W + kc * 8) * 4, b0, b1, b2, b3);
                #pragma unroll
                for (int mt = 0; mt < MT; mt++) {
                    float* a = acc[mt * 4 + nt];
                    mma16816(a, fah[mt][0], fah[mt][1], fah[mt][2], fah[mt][3], b0, b1);
                    mma16816(a, fah[mt][0], fah[mt][1], fah[mt][2], fah[mt][3], b2, b3);
                    mma16816(a, fal[mt][0], fal[mt][1], fal[mt][2], fal[mt][3], b0, b1);
                }
            }
        }
    }

    const float scale = (z == 0) ? qscale : 1.0f;
    #pragma unroll
    for (int mt = 0; mt < MT; mt++) {
        int row0 = m0 + wm * (16 * MT) + mt * 16 + g;
        #pragma unroll
        for (int nt = 0; nt < 4; nt++) {
            int col = c0 + wn * 32 + nt * 8 + 2 * t;
            float* a = acc[mt * 4 + nt];
            if (Cf) {
                float b0 = bias ? bias[col] : 0.f;
                float b1 = bias ? bias[col + 1] : 0.f;
                *reinterpret_cast<float2*>(Cf + (size_t)row0 * D_ + col) =
                    make_float2(a[0] + b0, a[1] + b1);
                *reinterpret_cast<float2*>(Cf + (size_t)(row0 + 8) * D_ + col) =
                    make_float2(a[2] + b0, a[3] + b1);
            } else {
                uint32_t h0, l0, h1, l1;
                pack_split(a[0] * scale, a[1] * scale, h0, l0);
                pack_split(a[2] * scale, a[3] * scale, h1, l1);
                size_t o0 = (size_t)z * MD_ + (size_t)row0 * D_ + col;
                size_t o1 = (size_t)z * MD_ + (size_t)(row0 + 8) * D_ + col;
                *reinterpret_cast<uint32_t*>(Ch + o0) = h0;
                *reinterpret_cast<uint32_t*>(Cl + o0) = l0;
                *reinterpret_cast<uint32_t*>(Ch + o1) = h1;
                *reinterpret_cast<uint32_t*>(Cl + o1) = l1;
            }
        }
    }
}

#define SMEM_GEMM4 (2 * (2 * 128 * PS_W + 2 * 128 * PS_W) * 4)      // 81920

// ---------------------------------------------------------------------------
// attn (EXACT R13 best config): 128 threads (4 warps), q-tile 128 (32 rows/
// warp, B-frag reuse x2), KV tile 32, double-buffered cp.async, 3 CTAs/SM.
// ---------------------------------------------------------------------------
#define AS_W 36
#define KT_ 32
#define A_KARR (KT_ * AS_W)                 // 1152 words
#define A_STAGE (4 * A_KARR)                // 4608 words / stage
#define A_QWORDS (2 * 128 * AS_W)           // 9216 words
#define SMEM_ATTN ((A_QWORDS + 2 * A_STAGE) * 4)   // 73728 B

__global__ __launch_bounds__(128, 3)
void attn_mma(const __nv_bfloat16* __restrict__ Qh, const __nv_bfloat16* __restrict__ Ql,
              const __nv_bfloat16* __restrict__ Kh, const __nv_bfloat16* __restrict__ Kl,
              const __nv_bfloat16* __restrict__ Vh, const __nv_bfloat16* __restrict__ Vl,
              __nv_bfloat16* __restrict__ Oh, __nv_bfloat16* __restrict__ Ol)
{
    extern __shared__ __align__(16) uint32_t sm[];

    const int tid = threadIdx.x;
    const int w = tid >> 5, lane = tid & 31, g = lane >> 2, t = lane & 3;
    const int n0 = blockIdx.x * 128;
    const int h = blockIdx.y, b = blockIdx.z;
    const size_t rs = (size_t)H_ * HS_;   // 512
    const size_t qbase = (((size_t)b * T_ + n0) * H_ + h) * HS_;
    const size_t kbase = ((size_t)b * S_) * rs + (size_t)h * HS_;

    const uint32_t smb = (uint32_t)__cvta_generic_to_shared(sm);
    const int r_ld = tid >> 3, c8_ld = tid & 7;   // 16 rows per 128-thr pass

    auto issue_kv = [&](int it, int st) {
        uint32_t base = smb + (A_QWORDS + st * A_STAGE) * 4;
        const size_t kb = kbase + (size_t)(it * KT_) * rs;
        #pragma unroll
        for (int i = 0; i < 2; i++) {
            int r = r_ld + i * 16;
            uint32_t d = base + r * (AS_W * 4) + c8_ld * 16;
            size_t src = kb + (size_t)r * rs + c8_ld * 8;
            cp16(d,                  Kh + src);
            cp16(d + A_KARR * 4,     Kl + src);
            cp16(d + 2 * A_KARR * 4, Vh + src);
            cp16(d + 3 * A_KARR * 4, Vl + src);
        }
    };

    // ---- Q tile (128x64 hi/lo) + first KV stage via cp.async ----
    {
        #pragma unroll
        for (int i = 0; i < 8; i++) {
            int r = r_ld + i * 16;
            uint32_t d = smb + r * (AS_W * 4) + c8_ld * 16;
            size_t src = qbase + (size_t)r * rs + c8_ld * 8;
            cp16(d, Qh + src);
            cp16(d + 128 * AS_W * 4, Ql + src);
        }
        issue_kv(0, 0);
        CP_COMMIT();
    }

    const int rowA = w * 32;    // 32 q-rows per warp

    const int mLd = lane >> 3, rLd = lane & 7;
    const uint32_t qA_hi = smb + ((rowA + (mLd & 1) * 8 + rLd) * AS_W + (mLd >> 1) * 4) * 4;
    const uint32_t qA_lo = qA_hi + 128 * AS_W * 4;
    const uint32_t bSkelK = (rLd * AS_W + (mLd & 1) * 4 + ((mLd >> 1) ? A_KARR : 0)) * 4;
    const uint32_t bSkelV = (((mLd & 1) * 8 + rLd) * AS_W + ((mLd >> 1) ? A_KARR : 0)) * 4;

    float oacc[2][8][4];
    #pragma unroll
    for (int mf = 0; mf < 2; mf++)
        #pragma unroll
        for (int ot = 0; ot < 8; ot++)
            #pragma unroll
            for (int j = 0; j < 4; j++) oacc[mf][ot][j] = 0.f;
    float ls[2][2] = {{0.f, 0.f}, {0.f, 0.f}};

    for (int it = 0; it < S_ / KT_; ++it) {
        CP_WAIT0();
        __syncthreads();
        if (it + 1 < S_ / KT_) { issue_kv(it + 1, (it + 1) & 1); CP_COMMIT(); }

        const uint32_t kvb = smb + (A_QWORDS + (it & 1) * A_STAGE) * 4;
        const uint32_t vbb = kvb + 2 * A_KARR * 4;

        // ---- S = Q K^T (32 s-cols; 2 m-frags share each B-fragment) ----
        float acc[2][4][4];
        #pragma unroll
        for (int mf = 0; mf < 2; mf++)
            #pragma unroll
            for (int nt = 0; nt < 4; nt++)
                #pragma unroll
                for (int j = 0; j < 4; j++) acc[mf][nt][j] = 0.f;

        #pragma unroll
        for (int kc = 0; kc < 4; kc++) {
            uint32_t ah[2][4], al[2][4];
            #pragma unroll
            for (int mf = 0; mf < 2; mf++) {
                uint32_t ao = (uint32_t)(mf * 16 * AS_W * 4) + kc * 32;
                ldsm4(qA_hi + ao, ah[mf][0], ah[mf][1], ah[mf][2], ah[mf][3]);
                ldsm4(qA_lo + ao, al[mf][0], al[mf][1], al[mf][2], al[mf][3]);
            }
            #pragma unroll
            for (int nt = 0; nt < 4; nt++) {
                uint32_t b0, b1, b2, b3;
                ldsm4(kvb + bSkelK + (nt * 8 * AS_W + kc * 8) * 4, b0, b1, b2, b3);
                #pragma unroll
                for (int mf = 0; mf < 2; mf++) {
                    mma16816(acc[mf][nt], ah[mf][0], ah[mf][1], ah[mf][2], ah[mf][3], b0, b1);
                    mma16816(acc[mf][nt], ah[mf][0], ah[mf][1], ah[mf][2], ah[mf][3], b2, b3);
                    mma16816(acc[mf][nt], al[mf][0], al[mf][1], al[mf][2], al[mf][3], b0, b1);
                }
            }
        }

        // ---- softmax: p = 2^s (log2e pre-folded into q scale) ----
        #pragma unroll
        for (int mf = 0; mf < 2; mf++)
            #pragma unroll
            for (int nt = 0; nt < 4; nt++) {
                float p0 = ex2f(acc[mf][nt][0]);
                float p1 = ex2f(acc[mf][nt][1]);
                float p2 = ex2f(acc[mf][nt][2]);
                float p3 = ex2f(acc[mf][nt][3]);
                ls[mf][0] += p0 + p1;
                ls[mf][1] += p2 + p3;
                acc[mf][nt][0] = p0; acc[mf][nt][1] = p1;
                acc[mf][nt][2] = p2; acc[mf][nt][3] = p3;
            }

        // ---- O += P V (K-dim = 32: 2 kc chunks) ----
        #pragma unroll
        for (int kc = 0; kc < 2; kc++) {
            uint32_t ph[2][4], pl[2][4];
            #pragma unroll
            for (int mf = 0; mf < 2; mf++) {
                pack_split(acc[mf][2 * kc][0],     acc[mf][2 * kc][1],     ph[mf][0], pl[mf][0]);
                pack_split(acc[mf][2 * kc][2],     acc[mf][2 * kc][3],     ph[mf][1], pl[mf][1]);
                pack_split(acc[mf][2 * kc + 1][0], acc[mf][2 * kc + 1][1], ph[mf][2], pl[mf][2]);
                pack_split(acc[mf][2 * kc + 1][2], acc[mf][2 * kc + 1][3], ph[mf][3], pl[mf][3]);
            }
            #pragma unroll
            for (int ot = 0; ot < 8; ot++) {
                uint32_t b0, b1, b2, b3;
                ldsm4t(vbb + bSkelV + (kc * 16 * AS_W + ot * 4) * 4, b0, b1, b2, b3);
                #pragma unroll
                for (int mf = 0; mf < 2; mf++) {
                    mma16816(oacc[mf][ot], ph[mf][0], ph[mf][1], ph[mf][2], ph[mf][3], b0, b1);
                    mma16816(oacc[mf][ot], ph[mf][0], ph[mf][1], ph[mf][2], ph[mf][3], b2, b3);
                    mma16816(oacc[mf][ot], pl[mf][0], pl[mf][1], pl[mf][2], pl[mf][3], b0, b1);
                }
            }
        }
    }

    // ---- normalize, split, write mh ----
    #pragma unroll
    for (int mf = 0; mf < 2; mf++) {
        ls[mf][0] += __shfl_xor_sync(0xffffffffu, ls[mf][0], 1);
        ls[mf][0] += __shfl_xor_sync(0xffffffffu, ls[mf][0], 2);
        ls[mf][1] += __shfl_xor_sync(0xffffffffu, ls[mf][1], 1);
        ls[mf][1] += __shfl_xor_sync(0xffffffffu, ls[mf][1], 2);
        const float inv0 = 1.f / ls[mf][0];
        const float inv1 = 1.f / ls[mf][1];

        size_t or0 = qbase + (size_t)(rowA + mf * 16 + g) * rs;
        size_t or1 = qbase + (size_t)(rowA + mf * 16 + g + 8) * rs;
        #pragma unroll
        for (int ot = 0; ot < 8; ot++) {
            uint32_t h0, l0, h1, l1;
            pack_split(oacc[mf][ot][0] * inv0, oacc[mf][ot][1] * inv0, h0, l0);
            pack_split(oacc[mf][ot][2] * inv1, oacc[mf][ot][3] * inv1, h1, l1);
            int col = ot * 8 + 2 * t;
            *reinterpret_cast<uint32_t*>(Oh + or0 + col) = h0;
            *reinterpret_cast<uint32_t*>(Ol + or0 + col) = l0;
            *reinterpret_cast<uint32_t*>(Oh + or1 + col) = h1;
            *reinterpret_cast<uint32_t*>(Ol + or1 + col) = l1;
        }
    }
}

// ---------------------------------------------------------------------------
// Host launcher
// ---------------------------------------------------------------------------
extern "C" void kernel_launch(void* const* d_in, const int* in_sizes, int n_in,
                              void* d_out, int out_size)
{
    const float* query = (const float*)d_in[0];
    const float* key   = (const float*)d_in[1];
    const float* value = (const float*)d_in[2];
    const float* qkern = (const float*)d_in[3];
    const float* kkern = (const float*)d_in[4];
    const float* vkern = (const float*)d_in[5];
    const float* pkern = (const float*)d_in[6];
    const float* pbias = (const float*)d_in[7];
    float* out = (float*)d_out;

    __nv_bfloat16 *acth, *actl, *wth, *wtl, *qkvh, *qkvl, *mhh, *mhl;
    cudaGetSymbolAddress((void**)&acth, g_acth);
    cudaGetSymbolAddress((void**)&actl, g_actl);
    cudaGetSymbolAddress((void**)&wth,  g_wth);
    cudaGetSymbolAddress((void**)&wtl,  g_wtl);
    cudaGetSymbolAddress((void**)&qkvh, g_qkvh);
    cudaGetSymbolAddress((void**)&qkvl, g_qkvl);
    cudaGetSymbolAddress((void**)&mhh,  g_mhh);
    cudaGetSymbolAddress((void**)&mhl,  g_mhl);

    cudaFuncSetAttribute(gemm_bf16<4>, cudaFuncAttributeMaxDynamicSharedMemorySize, SMEM_GEMM4);
    cudaFuncSetAttribute(attn_mma,     cudaFuncAttributeMaxDynamicSharedMemorySize, SMEM_ATTN);

    // 1. one-time conversions
    prep_act<<<dim3(2048, 1, 3), 256>>>(query, key, value);
    prep_w  <<<dim3(64, 1, 4),   256>>>(qkern, kkern, vkern, pkern);

    // 2. fused QKV projection (128x128 tiles: half the A re-reads of 128x64);
    //    q scale = (1/sqrt(HS)) * log2(e) for exp2 softmax
    const float qsc = 0.125f * 1.4426950408889634f;
    gemm_bf16<4><<<dim3(32, 4, 3), 256, SMEM_GEMM4>>>(acth, actl, wth, wtl,
                                                      qkvh, qkvl, nullptr, nullptr, qsc);

    // 3. attention (exact R13 best: 256 CTAs x 128 threads, KV 32, 3 CTAs/SM)
    attn_mma<<<dim3(16, 8, 2), 128, SMEM_ATTN>>>(qkvh, qkvl,
                                                 qkvh + MD_, qkvl + MD_,
                                                 qkvh + 2 * MD_, qkvl + 2 * MD_,
                                                 mhh, mhl);

    // 4. output projection (fp32 + bias)
    gemm_bf16<4><<<dim3(32, 4, 1), 256, SMEM_GEMM4>>>(mhh, mhl, wth + 3 * DD_, wtl + 3 * DD_,
                                                      nullptr, nullptr, out, pbias, 1.0f);
}

// round 17
// speedup vs baseline: 1.0953x; 1.0346x over previous
#include <cuda_runtime.h>
#include <cuda_bf16.h>
#include <cstdint>

#define B_  2
#define T_  2048
#define S_  2048
#define D_  512
#define H_  8
#define HS_ 64
#define M_  (B_*T_)                 // 4096 rows
#define MD_ ((size_t)M_*D_)         // 2097152
#define DD_ ((size_t)D_*D_)         // 262144

// Scratch (allocations are forbidden; use device globals). Split-bf16 pairs.
__device__ __nv_bfloat16 g_acth[3*MD_], g_actl[3*MD_];   // converted inputs
__device__ __nv_bfloat16 g_wth [4*DD_], g_wtl [4*DD_];   // transposed weights [c][k]
__device__ __nv_bfloat16 g_qkvh[3*MD_], g_qkvl[3*MD_];   // q,k,v  [b][n][h][o]
__device__ __nv_bfloat16 g_mhh [MD_],   g_mhl [MD_];     // attention output

// ---------------------------------------------------------------------------
// helpers
// ---------------------------------------------------------------------------
__device__ __forceinline__ void mma16816(float c[4],
    uint32_t a0, uint32_t a1, uint32_t a2, uint32_t a3,
    uint32_t b0, uint32_t b1)
{
    asm volatile(
        "mma.sync.aligned.m16n8k16.row.col.f32.bf16.bf16.f32 "
        "{%0,%1,%2,%3}, {%4,%5,%6,%7}, {%8,%9}, {%0,%1,%2,%3};"
        : "+f"(c[0]), "+f"(c[1]), "+f"(c[2]), "+f"(c[3])
        : "r"(a0), "r"(a1), "r"(a2), "r"(a3), "r"(b0), "r"(b1));
}

__device__ __forceinline__ void ldsm4(uint32_t addr,
    uint32_t& r0, uint32_t& r1, uint32_t& r2, uint32_t& r3)
{
    asm volatile("ldmatrix.sync.aligned.m8n8.x4.shared.b16 {%0,%1,%2,%3}, [%4];"
        : "=r"(r0), "=r"(r1), "=r"(r2), "=r"(r3) : "r"(addr));
}

__device__ __forceinline__ void ldsm4t(uint32_t addr,
    uint32_t& r0, uint32_t& r1, uint32_t& r2, uint32_t& r3)
{
    asm volatile("ldmatrix.sync.aligned.m8n8.x4.trans.shared.b16 {%0,%1,%2,%3}, [%4];"
        : "=r"(r0), "=r"(r1), "=r"(r2), "=r"(r3) : "r"(addr));
}

__device__ __forceinline__ float ex2f(float x)
{
    float y;
    asm("ex2.approx.f32 %0, %1;" : "=f"(y) : "f"(x));
    return y;
}

__device__ __forceinline__ void pack_split(float a, float b, uint32_t& h, uint32_t& l)
{
    __nv_bfloat162 hh = __floats2bfloat162_rn(a, b);
    float fa = __bfloat162float(hh.x), fb = __bfloat162float(hh.y);
    __nv_bfloat162 ll = __floats2bfloat162_rn(a - fa, b - fb);
    h = *reinterpret_cast<uint32_t*>(&hh);
    l = *reinterpret_cast<uint32_t*>(&ll);
}

__device__ __forceinline__ void cp16(uint32_t dst, const void* src)
{
    asm volatile("cp.async.cg.shared.global [%0], [%1], 16;" :: "r"(dst), "l"(src));
}
#define CP_COMMIT() asm volatile("cp.async.commit_group;" ::: "memory")
#define CP_WAIT0()  asm volatile("cp.async.wait_group 0;" ::: "memory")

// ---------------------------------------------------------------------------
// prep_act: fp32 inputs -> split bf16 (one-time)
// ---------------------------------------------------------------------------
__global__ __launch_bounds__(256)
void prep_act(const float* __restrict__ q, const float* __restrict__ k,
              const float* __restrict__ v)
{
    int z = blockIdx.z;
    const float* in = (z == 0) ? q : (z == 1) ? k : v;
    size_t e = (size_t)blockIdx.x * 256 + threadIdx.x;    // float4 index
    float4 a = reinterpret_cast<const float4*>(in)[e];
    uint32_t h0, l0, h1, l1;
    pack_split(a.x, a.y, h0, l0);
    pack_split(a.z, a.w, h1, l1);
    reinterpret_cast<uint2*>(g_acth + (size_t)z * MD_)[e] = make_uint2(h0, h1);
    reinterpret_cast<uint2*>(g_actl + (size_t)z * MD_)[e] = make_uint2(l0, l1);
}

// ---------------------------------------------------------------------------
// prep_w: weights -> transposed split bf16 Wt[c][k] (one-time)
// ---------------------------------------------------------------------------
__global__ __launch_bounds__(256)
void prep_w(const float* __restrict__ qk, const float* __restrict__ kk,
            const float* __restrict__ vk, const float* __restrict__ pk)
{
    __shared__ float ts[64 * 66];
    const int z = blockIdx.z;
    const int x = blockIdx.x;      // 0..63
    const int tid = threadIdx.x;
    const float* in = (z == 0) ? qk : (z == 1) ? kk : (z == 2) ? vk : pk;
    int k0, cbase;
    if (z < 3) { k0 = (x & 7) * 64; cbase = (x >> 3) * 64; }
    else       { k0 = (x >> 3) * 64; cbase = (x & 7) * 64; }

    #pragma unroll
    for (int it = 0; it < 4; it++) {
        int e = tid + it * 256;
        int i = e >> 4, j4 = e & 15;
        float4 a;
        if (z < 3)
            a = *reinterpret_cast<const float4*>(in + (size_t)(x >> 3) * (D_ * HS_)
                                                 + (size_t)(k0 + i) * HS_ + j4 * 4);
        else
            a = *reinterpret_cast<const float4*>(in + (size_t)(k0 + i) * D_ + cbase + j4 * 4);
        int wo = i * 66 + j4 * 4;
        *reinterpret_cast<float2*>(ts + wo)     = make_float2(a.x, a.y);
        *reinterpret_cast<float2*>(ts + wo + 2) = make_float2(a.z, a.w);
    }
    __syncthreads();

    #pragma unroll
    for (int it = 0; it < 2; it++) {
        int e = tid + it * 256;
        int o = e >> 3, k8 = e & 7;
        uint32_t hw[4], lw[4];
        #pragma unroll
        for (int p = 0; p < 4; p++) {
            float f0 = ts[(k8 * 8 + 2 * p)     * 66 + o];
            float f1 = ts[(k8 * 8 + 2 * p + 1) * 66 + o];
            pack_split(f0, f1, hw[p], lw[p]);
        }
        size_t off = (size_t)z * DD_ + (size_t)(cbase + o) * D_ + k0 + k8 * 8;
        *reinterpret_cast<uint4*>(g_wth + off) = *reinterpret_cast<uint4*>(hw);
        *reinterpret_cast<uint4*>(g_wtl + off) = *reinterpret_cast<uint4*>(lw);
    }
}

// ---------------------------------------------------------------------------
// gemm_bf16: CTA tile 64(M) x 128(N), K-tile 32, 128 threads (4 warps, 1m x
// 4n, warp tile 64x32, MT=4), cp.async 2-stage pipeline, ldmatrix loads.
// 3 CTAs/SM (smem 61.4KB, regs <= 170). Smooths QKV/out wave quantization.
// ---------------------------------------------------------------------------
#define PS_W 20
#define G_AROW 64
#define G_A_ARR (G_AROW * PS_W)             // 1280 words
#define G_W_ARR (128 * PS_W)                // 2560 words
#define G_STAGE (2 * G_A_ARR + 2 * G_W_ARR) // 7680 words
#define SMEM_GEMM (2 * G_STAGE * 4)         // 61440 B

__global__ __launch_bounds__(128, 3)
void gemm_bf16(const __nv_bfloat16* __restrict__ Ah, const __nv_bfloat16* __restrict__ Al,
               const __nv_bfloat16* __restrict__ Wth, const __nv_bfloat16* __restrict__ Wtl,
               __nv_bfloat16* __restrict__ Ch, __nv_bfloat16* __restrict__ Cl,
               float* __restrict__ Cf, const float* __restrict__ bias, float qscale)
{
    extern __shared__ __align__(16) uint32_t sm[];

    const int z = blockIdx.z;
    Ah  += (size_t)z * MD_;  Al  += (size_t)z * MD_;
    Wth += (size_t)z * DD_;  Wtl += (size_t)z * DD_;

    const int tid = threadIdx.x;
    const int wn = tid >> 5, lane = tid & 31, g = lane >> 2, t = lane & 3;
    const int m0 = blockIdx.x * 64, c0 = blockIdx.y * 128;

    const uint32_t smb = (uint32_t)__cvta_generic_to_shared(sm);
    const int r_ld = tid >> 2, c4_ld = tid & 3;   // 32 rows per pass, 4 cp/row

    auto issue = [&](int kt, int st) {
        uint32_t base = smb + st * (G_STAGE * 4);
        #pragma unroll
        for (int i = 0; i < 2; i++) {             // A: 64 rows hi+lo
            int r = r_ld + i * 32;
            uint32_t d = base + r * (PS_W * 4) + c4_ld * 16;
            size_t ga = (size_t)(m0 + r) * D_ + kt + c4_ld * 8;
            cp16(d,               Ah + ga);
            cp16(d + G_A_ARR * 4, Al + ga);
        }
        #pragma unroll
        for (int i = 0; i < 4; i++) {             // W: 128 rows hi+lo
            int r = r_ld + i * 32;
            uint32_t d = base + (2 * G_A_ARR) * 4 + r * (PS_W * 4) + c4_ld * 16;
            size_t gw = (size_t)(c0 + r) * D_ + kt + c4_ld * 8;
            cp16(d,               Wth + gw);
            cp16(d + G_W_ARR * 4, Wtl + gw);
        }
    };

    const int mLd = lane >> 3, rLd = lane & 7;
    const uint32_t aSkel = (((mLd & 1) * 8 + rLd) * PS_W + (mLd >> 1) * 4) * 4;
    const uint32_t bSkel = ((wn * 32 + rLd) * PS_W + (mLd & 1) * 4) * 4
                         + (2 * G_A_ARR + (mLd >> 1) * G_W_ARR) * 4;

    float acc[16][4];                 // [mt*4+nt][4]
    #pragma unroll
    for (int i = 0; i < 16; i++)
        #pragma unroll
        for (int j = 0; j < 4; j++) acc[i][j] = 0.f;

    issue(0, 0);
    CP_COMMIT();

    for (int it = 0; it < D_ / 32; ++it) {
        CP_WAIT0();
        __syncthreads();
        if (it + 1 < D_ / 32) { issue((it + 1) * 32, (it + 1) & 1); CP_COMMIT(); }

        const uint32_t stage = smb + (it & 1) * (G_STAGE * 4);

        #pragma unroll
        for (int kc = 0; kc < 2; kc++) {
            uint32_t fah[4][4], fal[4][4];
            #pragma unroll
            for (int mt = 0; mt < 4; mt++) {
                uint32_t a = stage + aSkel + (mt * 16 * PS_W + kc * 8) * 4;
                ldsm4(a,               fah[mt][0], fah[mt][1], fah[mt][2], fah[mt][3]);
                ldsm4(a + G_A_ARR * 4, fal[mt][0], fal[mt][1], fal[mt][2], fal[mt][3]);
            }
            #pragma unroll
            for (int nt = 0; nt < 4; nt++) {
                uint32_t b0, b1, b2, b3;
                ldsm4(stage + bSkel + (nt * 8 * PS_W + kc * 8) * 4, b0, b1, b2, b3);
                #pragma unroll
                for (int mt = 0; mt < 4; mt++) {
                    float* a = acc[mt * 4 + nt];
                    mma16816(a, fah[mt][0], fah[mt][1], fah[mt][2], fah[mt][3], b0, b1);
                    mma16816(a, fah[mt][0], fah[mt][1], fah[mt][2], fah[mt][3], b2, b3);
                    mma16816(a, fal[mt][0], fal[mt][1], fal[mt][2], fal[mt][3], b0, b1);
                }
            }
        }
    }

    const float scale = (z == 0) ? qscale : 1.0f;
    #pragma unroll
    for (int mt = 0; mt < 4; mt++) {
        int row0 = m0 + mt * 16 + g;
        #pragma unroll
        for (int nt = 0; nt < 4; nt++) {
            int col = c0 + wn * 32 + nt * 8 + 2 * t;
            float* a = acc[mt * 4 + nt];
            if (Cf) {
                float b0 = bias ? bias[col] : 0.f;
                float b1 = bias ? bias[col + 1] : 0.f;
                *reinterpret_cast<float2*>(Cf + (size_t)row0 * D_ + col) =
                    make_float2(a[0] + b0, a[1] + b1);
                *reinterpret_cast<float2*>(Cf + (size_t)(row0 + 8) * D_ + col) =
                    make_float2(a[2] + b0, a[3] + b1);
            } else {
                uint32_t h0, l0, h1, l1;
                pack_split(a[0] * scale, a[1] * scale, h0, l0);
                pack_split(a[2] * scale, a[3] * scale, h1, l1);
                size_t o0 = (size_t)z * MD_ + (size_t)row0 * D_ + col;
                size_t o1 = (size_t)z * MD_ + (size_t)(row0 + 8) * D_ + col;
                *reinterpret_cast<uint32_t*>(Ch + o0) = h0;
                *reinterpret_cast<uint32_t*>(Cl + o0) = l0;
                *reinterpret_cast<uint32_t*>(Ch + o1) = h1;
                *reinterpret_cast<uint32_t*>(Cl + o1) = l1;
            }
        }
    }
}

// ---------------------------------------------------------------------------
// attn (EXACT R13/R16 best config): 128 threads (4 warps), q-tile 128
// (32 rows/warp, B-frag reuse x2), KV tile 32, double-buffered, 3 CTAs/SM.
// ---------------------------------------------------------------------------
#define AS_W 36
#define KT_ 32
#define A_KARR (KT_ * AS_W)                 // 1152 words
#define A_STAGE (4 * A_KARR)                // 4608 words / stage
#define A_QWORDS (2 * 128 * AS_W)           // 9216 words
#define SMEM_ATTN ((A_QWORDS + 2 * A_STAGE) * 4)   // 73728 B

__global__ __launch_bounds__(128, 3)
void attn_mma(const __nv_bfloat16* __restrict__ Qh, const __nv_bfloat16* __restrict__ Ql,
              const __nv_bfloat16* __restrict__ Kh, const __nv_bfloat16* __restrict__ Kl,
              const __nv_bfloat16* __restrict__ Vh, const __nv_bfloat16* __restrict__ Vl,
              __nv_bfloat16* __restrict__ Oh, __nv_bfloat16* __restrict__ Ol)
{
    extern __shared__ __align__(16) uint32_t sm[];

    const int tid = threadIdx.x;
    const int w = tid >> 5, lane = tid & 31, g = lane >> 2, t = lane & 3;
    const int n0 = blockIdx.x * 128;
    const int h = blockIdx.y, b = blockIdx.z;
    const size_t rs = (size_t)H_ * HS_;   // 512
    const size_t qbase = (((size_t)b * T_ + n0) * H_ + h) * HS_;
    const size_t kbase = ((size_t)b * S_) * rs + (size_t)h * HS_;

    const uint32_t smb = (uint32_t)__cvta_generic_to_shared(sm);
    const int r_ld = tid >> 3, c8_ld = tid & 7;   // 16 rows per 128-thr pass

    auto issue_kv = [&](int it, int st) {
        uint32_t base = smb + (A_QWORDS + st * A_STAGE) * 4;
        const size_t kb = kbase + (size_t)(it * KT_) * rs;
        #pragma unroll
        for (int i = 0; i < 2; i++) {
            int r = r_ld + i * 16;
            uint32_t d = base + r * (AS_W * 4) + c8_ld * 16;
            size_t src = kb + (size_t)r * rs + c8_ld * 8;
            cp16(d,                  Kh + src);
            cp16(d + A_KARR * 4,     Kl + src);
            cp16(d + 2 * A_KARR * 4, Vh + src);
            cp16(d + 3 * A_KARR * 4, Vl + src);
        }
    };

    // ---- Q tile (128x64 hi/lo) + first KV stage via cp.async ----
    {
        #pragma unroll
        for (int i = 0; i < 8; i++) {
            int r = r_ld + i * 16;
            uint32_t d = smb + r * (AS_W * 4) + c8_ld * 16;
            size_t src = qbase + (size_t)r * rs + c8_ld * 8;
            cp16(d, Qh + src);
            cp16(d + 128 * AS_W * 4, Ql + src);
        }
        issue_kv(0, 0);
        CP_COMMIT();
    }

    const int rowA = w * 32;    // 32 q-rows per warp

    const int mLd = lane >> 3, rLd = lane & 7;
    const uint32_t qA_hi = smb + ((rowA + (mLd & 1) * 8 + rLd) * AS_W + (mLd >> 1) * 4) * 4;
    const uint32_t qA_lo = qA_hi + 128 * AS_W * 4;
    const uint32_t bSkelK = (rLd * AS_W + (mLd & 1) * 4 + ((mLd >> 1) ? A_KARR : 0)) * 4;
    const uint32_t bSkelV = (((mLd & 1) * 8 + rLd) * AS_W + ((mLd >> 1) ? A_KARR : 0)) * 4;

    float oacc[2][8][4];
    #pragma unroll
    for (int mf = 0; mf < 2; mf++)
        #pragma unroll
        for (int ot = 0; ot < 8; ot++)
            #pragma unroll
            for (int j = 0; j < 4; j++) oacc[mf][ot][j] = 0.f;
    float ls[2][2] = {{0.f, 0.f}, {0.f, 0.f}};

    for (int it = 0; it < S_ / KT_; ++it) {
        CP_WAIT0();
        __syncthreads();
        if (it + 1 < S_ / KT_) { issue_kv(it + 1, (it + 1) & 1); CP_COMMIT(); }

        const uint32_t kvb = smb + (A_QWORDS + (it & 1) * A_STAGE) * 4;
        const uint32_t vbb = kvb + 2 * A_KARR * 4;

        // ---- S = Q K^T (32 s-cols; 2 m-frags share each B-fragment) ----
        float acc[2][4][4];
        #pragma unroll
        for (int mf = 0; mf < 2; mf++)
            #pragma unroll
            for (int nt = 0; nt < 4; nt++)
                #pragma unroll
                for (int j = 0; j < 4; j++) acc[mf][nt][j] = 0.f;

        #pragma unroll
        for (int kc = 0; kc < 4; kc++) {
            uint32_t ah[2][4], al[2][4];
            #pragma unroll
            for (int mf = 0; mf < 2; mf++) {
                uint32_t ao = (uint32_t)(mf * 16 * AS_W * 4) + kc * 32;
                ldsm4(qA_hi + ao, ah[mf][0], ah[mf][1], ah[mf][2], ah[mf][3]);
                ldsm4(qA_lo + ao, al[mf][0], al[mf][1], al[mf][2], al[mf][3]);
            }
            #pragma unroll
            for (int nt = 0; nt < 4; nt++) {
                uint32_t b0, b1, b2, b3;
                ldsm4(kvb + bSkelK + (nt * 8 * AS_W + kc * 8) * 4, b0, b1, b2, b3);
                #pragma unroll
                for (int mf = 0; mf < 2; mf++) {
                    mma16816(acc[mf][nt], ah[mf][0], ah[mf][1], ah[mf][2], ah[mf][3], b0, b1);
                    mma16816(acc[mf][nt], ah[mf][0], ah[mf][1], ah[mf][2], ah[mf][3], b2, b3);
                    mma16816(acc[mf][nt], al[mf][0], al[mf][1], al[mf][2], al[mf][3], b0, b1);
                }
            }
        }

        // ---- softmax: p = 2^s (log2e pre-folded into q scale) ----
        #pragma unroll
        for (int mf = 0; mf < 2; mf++)
            #pragma unroll
            for (int nt = 0; nt < 4; nt++) {
                float p0 = ex2f(acc[mf][nt][0]);
                float p1 = ex2f(acc[mf][nt][1]);
                float p2 = ex2f(acc[mf][nt][2]);
                float p3 = ex2f(acc[mf][nt][3]);
                ls[mf][0] += p0 + p1;
                ls[mf][1] += p2 + p3;
                acc[mf][nt][0] = p0; acc[mf][nt][1] = p1;
                acc[mf][nt][2] = p2; acc[mf][nt][3] = p3;
            }

        // ---- O += P V (K-dim = 32: 2 kc chunks) ----
        #pragma unroll
        for (int kc = 0; kc < 2; kc++) {
            uint32_t ph[2][4], pl[2][4];
            #pragma unroll
            for (int mf = 0; mf < 2; mf++) {
                pack_split(acc[mf][2 * kc][0],     acc[mf][2 * kc][1],     ph[mf][0], pl[mf][0]);
                pack_split(acc[mf][2 * kc][2],     acc[mf][2 * kc][3],     ph[mf][1], pl[mf][1]);
                pack_split(acc[mf][2 * kc + 1][0], acc[mf][2 * kc + 1][1], ph[mf][2], pl[mf][2]);
                pack_split(acc[mf][2 * kc + 1][2], acc[mf][2 * kc + 1][3], ph[mf][3], pl[mf][3]);
            }
            #pragma unroll
            for (int ot = 0; ot < 8; ot++) {
                uint32_t b0, b1, b2, b3;
                ldsm4t(vbb + bSkelV + (kc * 16 * AS_W + ot * 4) * 4, b0, b1, b2, b3);
                #pragma unroll
                for (int mf = 0; mf < 2; mf++) {
                    mma16816(oacc[mf][ot], ph[mf][0], ph[mf][1], ph[mf][2], ph[mf][3], b0, b1);
                    mma16816(oacc[mf][ot], ph[mf][0], ph[mf][1], ph[mf][2], ph[mf][3], b2, b3);
                    mma16816(oacc[mf][ot], pl[mf][0], pl[mf][1], pl[mf][2], pl[mf][3], b0, b1);
                }
            }
        }
    }

    // ---- normalize, split, write mh ----
    #pragma unroll
    for (int mf = 0; mf < 2; mf++) {
        ls[mf][0] += __shfl_xor_sync(0xffffffffu, ls[mf][0], 1);
        ls[mf][0] += __shfl_xor_sync(0xffffffffu, ls[mf][0], 2);
        ls[mf][1] += __shfl_xor_sync(0xffffffffu, ls[mf][1], 1);
        ls[mf][1] += __shfl_xor_sync(0xffffffffu, ls[mf][1], 2);
        const float inv0 = 1.f / ls[mf][0];
        const float inv1 = 1.f / ls[mf][1];

        size_t or0 = qbase + (size_t)(rowA + mf * 16 + g) * rs;
        size_t or1 = qbase + (size_t)(rowA + mf * 16 + g + 8) * rs;
        #pragma unroll
        for (int ot = 0; ot < 8; ot++) {
            uint32_t h0, l0, h1, l1;
            pack_split(oacc[mf][ot][0] * inv0, oacc[mf][ot][1] * inv0, h0, l0);
            pack_split(oacc[mf][ot][2] * inv1, oacc[mf][ot][3] * inv1, h1, l1);
            int col = ot * 8 + 2 * t;
            *reinterpret_cast<uint32_t*>(Oh + or0 + col) = h0;
            *reinterpret_cast<uint32_t*>(Ol + or0 + col) = l0;
            *reinterpret_cast<uint32_t*>(Oh + or1 + col) = h1;
            *reinterpret_cast<uint32_t*>(Ol + or1 + col) = l1;
        }
    }
}

// ---------------------------------------------------------------------------
// Host launcher
// ---------------------------------------------------------------------------
extern "C" void kernel_launch(void* const* d_in, const int* in_sizes, int n_in,
                              void* d_out, int out_size)
{
    const float* query = (const float*)d_in[0];
    const float* key   = (const float*)d_in[1];
    const float* value = (const float*)d_in[2];
    const float* qkern = (const float*)d_in[3];
    const float* kkern = (const float*)d_in[4];
    const float* vkern = (const float*)d_in[5];
    const float* pkern = (const float*)d_in[6];
    const float* pbias = (const float*)d_in[7];
    float* out = (float*)d_out;

    __nv_bfloat16 *acth, *actl, *wth, *wtl, *qkvh, *qkvl, *mhh, *mhl;
    cudaGetSymbolAddress((void**)&acth, g_acth);
    cudaGetSymbolAddress((void**)&actl, g_actl);
    cudaGetSymbolAddress((void**)&wth,  g_wth);
    cudaGetSymbolAddress((void**)&wtl,  g_wtl);
    cudaGetSymbolAddress((void**)&qkvh, g_qkvh);
    cudaGetSymbolAddress((void**)&qkvl, g_qkvl);
    cudaGetSymbolAddress((void**)&mhh,  g_mhh);
    cudaGetSymbolAddress((void**)&mhl,  g_mhl);

    cudaFuncSetAttribute(gemm_bf16, cudaFuncAttributeMaxDynamicSharedMemorySize, SMEM_GEMM);
    cudaFuncSetAttribute(attn_mma,  cudaFuncAttributeMaxDynamicSharedMemorySize, SMEM_ATTN);

    // 1. one-time conversions
    prep_act<<<dim3(2048, 1, 3), 256>>>(query, key, value);
    prep_w  <<<dim3(64, 1, 4),   256>>>(qkern, kkern, vkern, pkern);

    // 2. fused QKV projection (64x128 tiles, 3 CTAs/SM, 768 CTAs -> 1.73
    //    smooth waves); q scale = (1/sqrt(HS)) * log2(e) for exp2 softmax
    const float qsc = 0.125f * 1.4426950408889634f;
    gemm_bf16<<<dim3(64, 4, 3), 128, SMEM_GEMM>>>(acth, actl, wth, wtl,
                                                  qkvh, qkvl, nullptr, nullptr, qsc);

    // 3. attention (exact R13 best: 256 CTAs x 128 threads, KV 32, 3 CTAs/SM)
    attn_mma<<<dim3(16, 8, 2), 128, SMEM_ATTN>>>(qkvh, qkvl,
                                                 qkvh + MD_, qkvl + MD_,
                                                 qkvh + 2 * MD_, qkvl + 2 * MD_,
                                                 mhh, mhl);

    // 4. output projection (64x128 tiles, 256 CTAs -> all SMs, interleaved)
    gemm_bf16<<<dim3(64, 4, 1), 128, SMEM_GEMM>>>(mhh, mhl, wth + 3 * DD_, wtl + 3 * DD_,
                                                  nullptr, nullptr, out, pbias, 1.0f);
}